// round 1
// baseline (speedup 1.0000x reference)
#include <cuda_runtime.h>
#include <math.h>

#define N     8192
#define FIN   512
#define FOUT  64
#define ALPHA 0.2f

#define S_SLICES 8
#define TI       128
#define TJ       32
#define JSLICE   (N / S_SLICES)   // 1024

// ---------------- device scratch (no runtime allocation allowed) ------------
__device__ float g_Wh[N * FOUT];                 // 2 MB
__device__ float g_s1[N];
__device__ float g_s2[N];
__device__ float g_s2max;
__device__ float g_pnum[S_SLICES * N * FOUT];    // 16.8 MB
__device__ float g_pden[S_SLICES * N];           // 256 KB

// ---------------- kernel 1: Wh = h @ W  (8192x512 @ 512x64) -----------------
#define GTI 64
#define GKC 64
__global__ __launch_bounds__(256) void k_gemm(const float* __restrict__ h,
                                              const float* __restrict__ W) {
    __shared__ float hs[GKC][GTI + 4];   // transposed [k][i], padded, 16B-aligned rows
    __shared__ float Ws[GKC][FOUT];

    int i0  = blockIdx.x * GTI;
    int tid = threadIdx.x;
    int ig  = tid >> 4;   // 0..15 -> i = ig*4
    int fg  = tid & 15;   // 0..15 -> f = fg*4

    float acc[4][4];
#pragma unroll
    for (int r = 0; r < 4; r++)
#pragma unroll
        for (int c = 0; c < 4; c++) acc[r][c] = 0.f;

    for (int k0 = 0; k0 < FIN; k0 += GKC) {
        // load h tile (transpose into [k][i])
#pragma unroll
        for (int q = 0; q < 4; q++) {
            int lin = tid + q * 256;          // 0..1023
            int ii  = lin >> 4;               // 0..63
            int kq  = (lin & 15) << 2;        // 0..60
            float4 v = *(const float4*)&h[(size_t)(i0 + ii) * FIN + k0 + kq];
            hs[kq + 0][ii] = v.x;
            hs[kq + 1][ii] = v.y;
            hs[kq + 2][ii] = v.z;
            hs[kq + 3][ii] = v.w;
        }
        // load W tile (same layout, direct copy)
#pragma unroll
        for (int q = 0; q < 4; q++) {
            int lin = tid + q * 256;
            int kk  = lin >> 4;
            int fq  = (lin & 15) << 2;
            *(float4*)&Ws[kk][fq] = *(const float4*)&W[(size_t)(k0 + kk) * FOUT + fq];
        }
        __syncthreads();
#pragma unroll
        for (int kk = 0; kk < GKC; kk++) {
            float4 av = *(float4*)&hs[kk][ig * 4];
            float4 bv = *(float4*)&Ws[kk][fg * 4];
            float ar[4] = {av.x, av.y, av.z, av.w};
            float br[4] = {bv.x, bv.y, bv.z, bv.w};
#pragma unroll
            for (int r = 0; r < 4; r++)
#pragma unroll
                for (int c = 0; c < 4; c++) acc[r][c] += ar[r] * br[c];
        }
        __syncthreads();
    }
#pragma unroll
    for (int r = 0; r < 4; r++) {
        float4 o = make_float4(acc[r][0], acc[r][1], acc[r][2], acc[r][3]);
        *(float4*)&g_Wh[(size_t)(i0 + ig * 4 + r) * FOUT + fg * 4] = o;
    }
}

// ---------------- kernel 2: s1 = Wh@a1, s2 = Wh@a2 (one warp per row) -------
__global__ __launch_bounds__(256) void k_s12(const float* __restrict__ a) {
    int warp = (blockIdx.x * blockDim.x + threadIdx.x) >> 5;
    int lane = threadIdx.x & 31;
    if (warp >= N) return;
    const float* whr = g_Wh + (size_t)warp * FOUT;
    float v0 = whr[lane], v1 = whr[lane + 32];
    float p1 = v0 * a[lane]      + v1 * a[lane + 32];
    float p2 = v0 * a[64 + lane] + v1 * a[96 + lane];
#pragma unroll
    for (int off = 16; off > 0; off >>= 1) {
        p1 += __shfl_down_sync(0xffffffffu, p1, off);
        p2 += __shfl_down_sync(0xffffffffu, p2, off);
    }
    if (lane == 0) { g_s1[warp] = p1; g_s2[warp] = p2; }
}

// ---------------- kernel 3: global max of s2 (single CTA, deterministic) ----
__global__ __launch_bounds__(256) void k_max() {
    __shared__ float sm[256];
    int tid = threadIdx.x;
    float m = -INFINITY;
    for (int i = tid; i < N; i += 256) m = fmaxf(m, g_s2[i]);
    sm[tid] = m;
    __syncthreads();
#pragma unroll
    for (int s = 128; s > 0; s >>= 1) {
        if (tid < s) sm[tid] = fmaxf(sm[tid], sm[tid + s]);
        __syncthreads();
    }
    if (tid == 0) g_s2max = sm[0];
}

// ---------------- kernel 4: fused masked-softmax attention (partials) -------
// grid = (N/TI) * S_SLICES CTAs, 128 threads.
// Each CTA: TI=128 rows i, one 1024-wide j-slice. Per-thread tile 8i x 8f.
__global__ __launch_bounds__(128, 4) void k_attn(const int* __restrict__ adj) {
    __shared__ float s1_sh[TI];
    __shared__ float m_sh[TI];
    __shared__ float s2_sh[JSLICE];          // 4 KB
    __shared__ float w_s[TJ][TI + 4];        // 32 x 132 floats (rows 16B-aligned)
    __shared__ float wh_s[TJ][FOUT];         // 8 KB

    int tile  = blockIdx.x >> 3;       // / S_SLICES
    int slice = blockIdx.x & (S_SLICES - 1);
    int i0 = tile * TI;
    int j0 = slice * JSLICE;
    int tid = threadIdx.x;

    float s2max = g_s2max;
    {
        float s1v = g_s1[i0 + tid];    // TI == blockDim.x
        s1_sh[tid] = s1v;
        float x = s1v + s2max;
        m_sh[tid] = fmaxf(x, ALPHA * x);
    }
#pragma unroll
    for (int q = 0; q < JSLICE / 128; q++)
        s2_sh[tid + q * 128] = g_s2[j0 + tid + q * 128];
    __syncthreads();

    int ig = tid >> 3;     // 0..15 -> i = ig*8
    int fg = tid & 7;      // 0..7  -> f = fg*8
    int jjw   = tid & 31;  // j-column this thread computes weights for
    int ibase = tid >> 5;  // 0..3

    float acc[8][8];
#pragma unroll
    for (int r = 0; r < 8; r++)
#pragma unroll
        for (int c = 0; c < 8; c++) acc[r][c] = 0.f;
    float den[8];
#pragma unroll
    for (int r = 0; r < 8; r++) den[r] = 0.f;

    for (int jt = 0; jt < JSLICE; jt += TJ) {
        // ---- load Wh tile (32 x 64 floats) ----
#pragma unroll
        for (int q = 0; q < 4; q++) {
            int lin = tid + q * 128;           // 0..511
            int r   = lin >> 4;                // 0..31
            int c   = (lin & 15) << 2;         // 0..60
            *(float4*)&wh_s[r][c] =
                *(const float4*)&g_Wh[(size_t)(j0 + jt + r) * FOUT + c];
        }
        // ---- compute attention weights for this 128x32 tile ----
        {
            float s2v = s2_sh[jt + jjw];
            const int* adjp = adj + (size_t)i0 * N + (j0 + jt + jjw);
#pragma unroll 8
            for (int k2 = 0; k2 < 32; k2++) {
                int ii = ibase + (k2 << 2);
                int av = adjp[(size_t)ii * N];
                float x = s1_sh[ii] + s2v;
                x = fmaxf(x, ALPHA * x);
                float w = (av > 0) ? __expf(x - m_sh[ii]) : 0.f;
                w_s[jjw][ii] = w;
            }
        }
        __syncthreads();
        // ---- FMA phase: acc[i][f] += w[i][j] * Wh[j][f] ----
#pragma unroll 4
        for (int jj = 0; jj < TJ; jj++) {
            float4 wa = *(float4*)&w_s[jj][ig * 8];
            float4 wb = *(float4*)&w_s[jj][ig * 8 + 4];
            float4 b0 = *(float4*)&wh_s[jj][fg * 8];
            float4 b1 = *(float4*)&wh_s[jj][fg * 8 + 4];
            float wr[8] = {wa.x, wa.y, wa.z, wa.w, wb.x, wb.y, wb.z, wb.w};
            float bv[8] = {b0.x, b0.y, b0.z, b0.w, b1.x, b1.y, b1.z, b1.w};
#pragma unroll
            for (int r = 0; r < 8; r++)
#pragma unroll
                for (int c = 0; c < 8; c++) acc[r][c] += wr[r] * bv[c];
            if (fg == 0) {
#pragma unroll
                for (int r = 0; r < 8; r++) den[r] += wr[r];
            }
        }
        __syncthreads();
    }

    // ---- epilogue: write per-slice partials ----
#pragma unroll
    for (int r = 0; r < 8; r++) {
        int i = i0 + ig * 8 + r;
        size_t base = ((size_t)slice * N + i) * FOUT + fg * 8;
        *(float4*)&g_pnum[base]     = make_float4(acc[r][0], acc[r][1], acc[r][2], acc[r][3]);
        *(float4*)&g_pnum[base + 4] = make_float4(acc[r][4], acc[r][5], acc[r][6], acc[r][7]);
    }
    if (fg == 0) {
#pragma unroll
        for (int r = 0; r < 8; r++)
            g_pden[(size_t)slice * N + i0 + ig * 8 + r] = den[r];
    }
}

// ---------------- kernel 5: combine slices, normalize, elu ------------------
__global__ __launch_bounds__(256) void k_reduce(float* __restrict__ out) {
    int t = blockIdx.x * blockDim.x + threadIdx.x;   // over N*FOUT/4
    if (t >= N * FOUT / 4) return;
    int i  = t >> 4;              // FOUT/4 == 16 float4 per row
    int c4 = (t & 15) << 2;
    float sx = 0.f, sy = 0.f, sz = 0.f, sw = 0.f, d = 0.f;
#pragma unroll
    for (int s = 0; s < S_SLICES; s++) {
        float4 v = *(const float4*)&g_pnum[((size_t)s * N + i) * FOUT + c4];
        sx += v.x; sy += v.y; sz += v.z; sw += v.w;
        d  += g_pden[(size_t)s * N + i];
    }
    float inv = 1.f / d;
    float ox = sx * inv, oy = sy * inv, oz = sz * inv, ow = sw * inv;
    float4 o;
    o.x = ox > 0.f ? ox : expm1f(ox);
    o.y = oy > 0.f ? oy : expm1f(oy);
    o.z = oz > 0.f ? oz : expm1f(oz);
    o.w = ow > 0.f ? ow : expm1f(ow);
    *(float4*)&out[(size_t)i * FOUT + c4] = o;
}

// ---------------------------------------------------------------------------
extern "C" void kernel_launch(void* const* d_in, const int* in_sizes, int n_in,
                              void* d_out, int out_size) {
    const float* h   = (const float*)d_in[0];   // 8192 x 512
    const float* W   = (const float*)d_in[1];   // 512 x 64
    const float* a   = (const float*)d_in[2];   // 128 x 1
    const int*   adj = (const int*)d_in[3];     // 8192 x 8192
    float* out = (float*)d_out;                 // 8192 x 64

    k_gemm<<<N / GTI, 256>>>(h, W);
    k_s12<<<N / 8, 256>>>(a);
    k_max<<<1, 256>>>();
    k_attn<<<(N / TI) * S_SLICES, 128>>>(adj);
    k_reduce<<<(N * FOUT / 4) / 256, 256>>>(out);
}

// round 2
// speedup vs baseline: 1.3902x; 1.3902x over previous
#include <cuda_runtime.h>
#include <math.h>

#define N     8192
#define FIN   512
#define FOUT  64
#define ALPHA 0.2f

#define S_SLICES 8
#define TI       128
#define TJ       32
#define JSLICE   (N / S_SLICES)   // 1024

typedef unsigned long long ull;

// ---------------- device scratch ------------------------------------------
__device__ float g_Wh[N * FOUT];                 // 2 MB
__device__ float g_s1[N];
__device__ float g_s2[N];
__device__ float g_s2max;
__device__ float g_E1[N], g_E2[N], g_F1[N], g_F2[N];
__device__ float g_pnum[S_SLICES * N * FOUT];    // 16.8 MB
__device__ float g_pden[S_SLICES * N];           // 256 KB

__forceinline__ __device__ void ffma2(ull& d, ull a, ull b) {
    asm("fma.rn.f32x2 %0, %1, %2, %3;" : "=l"(d) : "l"(a), "l"(b), "l"(d));
}
__forceinline__ __device__ ull pack2(float v) {
    ull r;
    asm("mov.b64 %0, {%1, %1};" : "=l"(r) : "f"(v));
    return r;
}

// ---------------- kernel 1: Wh = h @ W  (8192x512 @ 512x64) -----------------
#define GTI 64
#define GKC 64
__global__ __launch_bounds__(256) void k_gemm(const float* __restrict__ h,
                                              const float* __restrict__ W) {
    __shared__ float hs[GKC][GTI + 4];
    __shared__ float Ws[GKC][FOUT];

    int i0  = blockIdx.x * GTI;
    int tid = threadIdx.x;
    int ig  = tid >> 4;
    int fg  = tid & 15;

    float acc[4][4];
#pragma unroll
    for (int r = 0; r < 4; r++)
#pragma unroll
        for (int c = 0; c < 4; c++) acc[r][c] = 0.f;

    for (int k0 = 0; k0 < FIN; k0 += GKC) {
#pragma unroll
        for (int q = 0; q < 4; q++) {
            int lin = tid + q * 256;
            int ii  = lin >> 4;
            int kq  = (lin & 15) << 2;
            float4 v = *(const float4*)&h[(size_t)(i0 + ii) * FIN + k0 + kq];
            hs[kq + 0][ii] = v.x;
            hs[kq + 1][ii] = v.y;
            hs[kq + 2][ii] = v.z;
            hs[kq + 3][ii] = v.w;
        }
#pragma unroll
        for (int q = 0; q < 4; q++) {
            int lin = tid + q * 256;
            int kk  = lin >> 4;
            int fq  = (lin & 15) << 2;
            *(float4*)&Ws[kk][fq] = *(const float4*)&W[(size_t)(k0 + kk) * FOUT + fq];
        }
        __syncthreads();
#pragma unroll
        for (int kk = 0; kk < GKC; kk++) {
            float4 av = *(float4*)&hs[kk][ig * 4];
            float4 bv = *(float4*)&Ws[kk][fg * 4];
            float ar[4] = {av.x, av.y, av.z, av.w};
            float br[4] = {bv.x, bv.y, bv.z, bv.w};
#pragma unroll
            for (int r = 0; r < 4; r++)
#pragma unroll
                for (int c = 0; c < 4; c++) acc[r][c] += ar[r] * br[c];
        }
        __syncthreads();
    }
#pragma unroll
    for (int r = 0; r < 4; r++) {
        float4 o = make_float4(acc[r][0], acc[r][1], acc[r][2], acc[r][3]);
        *(float4*)&g_Wh[(size_t)(i0 + ig * 4 + r) * FOUT + fg * 4] = o;
    }
}

// ---------------- kernel 2: s1 = Wh@a1, s2 = Wh@a2 --------------------------
__global__ __launch_bounds__(256) void k_s12(const float* __restrict__ a) {
    int warp = (blockIdx.x * blockDim.x + threadIdx.x) >> 5;
    int lane = threadIdx.x & 31;
    if (warp >= N) return;
    const float* whr = g_Wh + (size_t)warp * FOUT;
    float v0 = whr[lane], v1 = whr[lane + 32];
    float p1 = v0 * a[lane]      + v1 * a[lane + 32];
    float p2 = v0 * a[64 + lane] + v1 * a[96 + lane];
#pragma unroll
    for (int off = 16; off > 0; off >>= 1) {
        p1 += __shfl_down_sync(0xffffffffu, p1, off);
        p2 += __shfl_down_sync(0xffffffffu, p2, off);
    }
    if (lane == 0) { g_s1[warp] = p1; g_s2[warp] = p2; }
}

// ---------------- kernel 3: global max of s2 --------------------------------
__global__ __launch_bounds__(256) void k_max() {
    __shared__ float sm[256];
    int tid = threadIdx.x;
    float m = -INFINITY;
    for (int i = tid; i < N; i += 256) m = fmaxf(m, g_s2[i]);
    sm[tid] = m;
    __syncthreads();
#pragma unroll
    for (int s = 128; s > 0; s >>= 1) {
        if (tid < s) sm[tid] = fmaxf(sm[tid], sm[tid + s]);
        __syncthreads();
    }
    if (tid == 0) g_s2max = sm[0];
}

// ---------------- kernel 3b: per-node softmax factors -----------------------
// exp(lrelu(s1_i+s2_j) - m_i) == max(E1_i*F1_j, E2_i*F2_j); all exponents <= 0.
__global__ __launch_bounds__(256) void k_factors() {
    int i = blockIdx.x * 256 + threadIdx.x;
    float s2m = g_s2max;
    float x = g_s1[i] + s2m;
    float m = fmaxf(x, ALPHA * x);
    g_E1[i] = expf(x - m);
    g_E2[i] = expf(ALPHA * x - m);
    float y = g_s2[i] - s2m;
    g_F1[i] = expf(y);
    g_F2[i] = expf(ALPHA * y);
}

// ---------------- kernel 4: fused attention (partials), FFMA2 core ----------
__global__ __launch_bounds__(128, 4) void k_attn(const int* __restrict__ adj) {
    __shared__ float E1_sh[TI], E2_sh[TI];
    __shared__ float F1_sh[JSLICE], F2_sh[JSLICE];   // 8 KB
    __shared__ float w_s[TJ][TI + 4];                // 16.9 KB
    __shared__ float wh_s[TJ][FOUT];                 // 8 KB

    int tile  = blockIdx.x >> 3;
    int slice = blockIdx.x & (S_SLICES - 1);
    int i0 = tile * TI;
    int j0 = slice * JSLICE;
    int tid = threadIdx.x;

    E1_sh[tid] = g_E1[i0 + tid];
    E2_sh[tid] = g_E2[i0 + tid];
#pragma unroll
    for (int q = 0; q < JSLICE / 128; q++) {
        F1_sh[tid + q * 128] = g_F1[j0 + tid + q * 128];
        F2_sh[tid + q * 128] = g_F2[j0 + tid + q * 128];
    }
    __syncthreads();

    // FMA-phase mapping: 8 i x 8 f per thread (f packed as 4 f32x2)
    int ig = tid >> 3;     // 0..15
    int fg = tid & 7;      // 0..7
    // w-phase mapping: jq = j4-group, iq: rows iq + 16*r
    int jq = tid & 7;      // j = jq*4 .. +3
    int iq = tid >> 3;     // rows iq + 16*r, r = 0..7

    ull acc[8][4];
#pragma unroll
    for (int r = 0; r < 8; r++)
#pragma unroll
        for (int c = 0; c < 4; c++) acc[r][c] = 0ull;
    float dpart[8];
#pragma unroll
    for (int r = 0; r < 8; r++) dpart[r] = 0.f;

    for (int jt = 0; jt < JSLICE; jt += TJ) {
        // ---- prefetch wh tile into regs (L2-hot) ----
        float4 whv[4];
#pragma unroll
        for (int q = 0; q < 4; q++) {
            int lin = tid + q * 128;
            int r   = lin >> 4;
            int c   = (lin & 15) << 2;
            whv[q] = *(const float4*)&g_Wh[(size_t)(j0 + jt + r) * FOUT + c];
        }
        // ---- weights: w = adj ? max(E1*F1, E2*F2) : 0  (no exp!) ----
        float f1[4], f2[4];
#pragma unroll
        for (int q = 0; q < 4; q++) {
            f1[q] = F1_sh[jt + jq * 4 + q];
            f2[q] = F2_sh[jt + jq * 4 + q];
        }
#pragma unroll
        for (int r = 0; r < 8; r++) {
            int il = iq + 16 * r;
            int4 av = *(const int4*)&adj[(size_t)(i0 + il) * N + j0 + jt + jq * 4];
            float e1 = E1_sh[il], e2 = E2_sh[il];
            float w0 = (av.x > 0) ? fmaxf(e1 * f1[0], e2 * f2[0]) : 0.f;
            float w1 = (av.y > 0) ? fmaxf(e1 * f1[1], e2 * f2[1]) : 0.f;
            float w2 = (av.z > 0) ? fmaxf(e1 * f1[2], e2 * f2[2]) : 0.f;
            float w3 = (av.w > 0) ? fmaxf(e1 * f1[3], e2 * f2[3]) : 0.f;
            dpart[r] += (w0 + w1) + (w2 + w3);
            w_s[jq * 4 + 0][il] = w0;
            w_s[jq * 4 + 1][il] = w1;
            w_s[jq * 4 + 2][il] = w2;
            w_s[jq * 4 + 3][il] = w3;
        }
        // ---- store wh tile ----
#pragma unroll
        for (int q = 0; q < 4; q++) {
            int lin = tid + q * 128;
            int r   = lin >> 4;
            int c   = (lin & 15) << 2;
            *(float4*)&wh_s[r][c] = whv[q];
        }
        __syncthreads();

        // ---- FFMA2 phase: acc[i][f2] += (w,w) * (wh_f, wh_f+1) ----
#pragma unroll 4
        for (int jj = 0; jj < TJ; jj++) {
            ulonglong2 b0 = *(ulonglong2*)&wh_s[jj][fg * 8];
            ulonglong2 b1 = *(ulonglong2*)&wh_s[jj][fg * 8 + 4];
            float4 wa = *(float4*)&w_s[jj][ig * 8];
            float4 wb = *(float4*)&w_s[jj][ig * 8 + 4];
            float wr[8] = {wa.x, wa.y, wa.z, wa.w, wb.x, wb.y, wb.z, wb.w};
#pragma unroll
            for (int r = 0; r < 8; r++) {
                ull wp = pack2(wr[r]);
                ffma2(acc[r][0], wp, b0.x);
                ffma2(acc[r][1], wp, b0.y);
                ffma2(acc[r][2], wp, b1.x);
                ffma2(acc[r][3], wp, b1.y);
            }
        }
        __syncthreads();
    }

    // ---- write numerator partials ----
#pragma unroll
    for (int r = 0; r < 8; r++) {
        int i = i0 + ig * 8 + r;
        size_t base = ((size_t)slice * N + i) * FOUT + fg * 8;
        *(ulonglong2*)&g_pnum[base]     = make_ulonglong2(acc[r][0], acc[r][1]);
        *(ulonglong2*)&g_pnum[base + 4] = make_ulonglong2(acc[r][2], acc[r][3]);
    }

    // ---- reduce denominator partials across the 8 jq owners per row ----
    float* den_sh = &w_s[0][0];    // reuse, [TI][9] layout
#pragma unroll
    for (int r = 0; r < 8; r++)
        den_sh[(iq + 16 * r) * 9 + jq] = dpart[r];
    __syncthreads();
    {
        float d = 0.f;
#pragma unroll
        for (int q = 0; q < 8; q++) d += den_sh[tid * 9 + q];
        g_pden[(size_t)slice * N + i0 + tid] = d;
    }
}

// ---------------- kernel 5: combine slices, normalize, elu ------------------
__global__ __launch_bounds__(256) void k_reduce(float* __restrict__ out) {
    int t = blockIdx.x * blockDim.x + threadIdx.x;
    if (t >= N * FOUT / 4) return;
    int i  = t >> 4;
    int c4 = (t & 15) << 2;
    float sx = 0.f, sy = 0.f, sz = 0.f, sw = 0.f, d = 0.f;
#pragma unroll
    for (int s = 0; s < S_SLICES; s++) {
        float4 v = *(const float4*)&g_pnum[((size_t)s * N + i) * FOUT + c4];
        sx += v.x; sy += v.y; sz += v.z; sw += v.w;
        d  += g_pden[(size_t)s * N + i];
    }
    float inv = 1.f / d;
    float ox = sx * inv, oy = sy * inv, oz = sz * inv, ow = sw * inv;
    float4 o;
    o.x = ox > 0.f ? ox : expm1f(ox);
    o.y = oy > 0.f ? oy : expm1f(oy);
    o.z = oz > 0.f ? oz : expm1f(oz);
    o.w = ow > 0.f ? ow : expm1f(ow);
    *(float4*)&out[(size_t)i * FOUT + c4] = o;
}

// ---------------------------------------------------------------------------
extern "C" void kernel_launch(void* const* d_in, const int* in_sizes, int n_in,
                              void* d_out, int out_size) {
    const float* h   = (const float*)d_in[0];
    const float* W   = (const float*)d_in[1];
    const float* a   = (const float*)d_in[2];
    const int*   adj = (const int*)d_in[3];
    float* out = (float*)d_out;

    k_gemm<<<N / GTI, 256>>>(h, W);
    k_s12<<<N / 8, 256>>>(a);
    k_max<<<1, 256>>>();
    k_factors<<<N / 256, 256>>>();
    k_attn<<<(N / TI) * S_SLICES, 128>>>(adj);
    k_reduce<<<(N * FOUT / 4) / 256, 256>>>(out);
}

// round 5
// speedup vs baseline: 1.8983x; 1.3655x over previous
#include <cuda_runtime.h>
#include <math.h>
#include <stdint.h>

#define N     8192
#define FIN   512
#define FOUT  64
#define ALPHA 0.2f

#define S_SLICES 8
#define TI       128
#define KT       32
#define JSLICE   (N / S_SLICES)   // 1024
#define NITER    (JSLICE / KT)    // 32

// ---------------- device scratch ------------------------------------------
__device__ float g_Wh[N * FOUT];                 // 2 MB
__device__ float g_s1[N];
__device__ float g_s2[N];
__device__ float g_s2max;
__device__ float g_E1[N], g_E2[N], g_F1[N], g_F2[N];
__device__ float g_pnum[S_SLICES * N * FOUT];    // 16.8 MB
__device__ float g_pden[S_SLICES * N];

__forceinline__ __device__ uint32_t cvt_tf32(float f) {
    uint32_t u; asm("cvt.rna.tf32.f32 %0, %1;" : "=r"(u) : "f"(f)); return u;
}

__forceinline__ __device__ void mma8(float* d, const uint32_t* a, const uint32_t* b) {
    asm volatile(
        "mma.sync.aligned.m16n8k8.row.col.f32.tf32.tf32.f32 "
        "{%0,%1,%2,%3}, {%4,%5,%6,%7}, {%8,%9}, {%0,%1,%2,%3};"
        : "+f"(d[0]), "+f"(d[1]), "+f"(d[2]), "+f"(d[3])
        : "r"(a[0]), "r"(a[1]), "r"(a[2]), "r"(a[3]), "r"(b[0]), "r"(b[1]));
}

// ---------------- kernel 1: Wh = h @ W --------------------------------------
#define GTI 64
#define GKC 64
__global__ __launch_bounds__(256) void k_gemm(const float* __restrict__ h,
                                              const float* __restrict__ W) {
    __shared__ float hs[GKC][GTI + 4];
    __shared__ float Ws[GKC][FOUT];
    int i0 = blockIdx.x * GTI, tid = threadIdx.x;
    int ig = tid >> 4, fg = tid & 15;
    float acc[4][4];
#pragma unroll
    for (int r = 0; r < 4; r++)
#pragma unroll
        for (int c = 0; c < 4; c++) acc[r][c] = 0.f;
    for (int k0 = 0; k0 < FIN; k0 += GKC) {
#pragma unroll
        for (int q = 0; q < 4; q++) {
            int lin = tid + q * 256, ii = lin >> 4, kq = (lin & 15) << 2;
            float4 v = *(const float4*)&h[(size_t)(i0 + ii) * FIN + k0 + kq];
            hs[kq + 0][ii] = v.x; hs[kq + 1][ii] = v.y;
            hs[kq + 2][ii] = v.z; hs[kq + 3][ii] = v.w;
        }
#pragma unroll
        for (int q = 0; q < 4; q++) {
            int lin = tid + q * 256, kk = lin >> 4, fq = (lin & 15) << 2;
            *(float4*)&Ws[kk][fq] = *(const float4*)&W[(size_t)(k0 + kk) * FOUT + fq];
        }
        __syncthreads();
#pragma unroll
        for (int kk = 0; kk < GKC; kk++) {
            float4 av = *(float4*)&hs[kk][ig * 4];
            float4 bv = *(float4*)&Ws[kk][fg * 4];
            float ar[4] = {av.x, av.y, av.z, av.w};
            float br[4] = {bv.x, bv.y, bv.z, bv.w};
#pragma unroll
            for (int r = 0; r < 4; r++)
#pragma unroll
                for (int c = 0; c < 4; c++) acc[r][c] += ar[r] * br[c];
        }
        __syncthreads();
    }
#pragma unroll
    for (int r = 0; r < 4; r++)
        *(float4*)&g_Wh[(size_t)(i0 + ig * 4 + r) * FOUT + fg * 4] =
            make_float4(acc[r][0], acc[r][1], acc[r][2], acc[r][3]);
}

// ---------------- kernel 2: s1 = Wh@a1, s2 = Wh@a2 --------------------------
__global__ __launch_bounds__(256) void k_s12(const float* __restrict__ a) {
    int warp = (blockIdx.x * blockDim.x + threadIdx.x) >> 5;
    int lane = threadIdx.x & 31;
    if (warp >= N) return;
    const float* whr = g_Wh + (size_t)warp * FOUT;
    float v0 = whr[lane], v1 = whr[lane + 32];
    float p1 = v0 * a[lane]      + v1 * a[lane + 32];
    float p2 = v0 * a[64 + lane] + v1 * a[96 + lane];
#pragma unroll
    for (int off = 16; off > 0; off >>= 1) {
        p1 += __shfl_down_sync(0xffffffffu, p1, off);
        p2 += __shfl_down_sync(0xffffffffu, p2, off);
    }
    if (lane == 0) { g_s1[warp] = p1; g_s2[warp] = p2; }
}

// ---------------- kernel 3: global max of s2 --------------------------------
__global__ __launch_bounds__(256) void k_max() {
    __shared__ float sm[256];
    int tid = threadIdx.x;
    float m = -INFINITY;
    for (int i = tid; i < N; i += 256) m = fmaxf(m, g_s2[i]);
    sm[tid] = m;
    __syncthreads();
#pragma unroll
    for (int s = 128; s > 0; s >>= 1) {
        if (tid < s) sm[tid] = fmaxf(sm[tid], sm[tid + s]);
        __syncthreads();
    }
    if (tid == 0) g_s2max = sm[0];
}

// ---------------- kernel 3b: per-node softmax factors -----------------------
// exp(lrelu(s1_i+s2_j) - m_i) == max(E1_i*F1_j, E2_i*F2_j); all exponents <= 0.
__global__ __launch_bounds__(256) void k_factors() {
    int i = blockIdx.x * 256 + threadIdx.x;
    float s2m = g_s2max;
    float x = g_s1[i] + s2m;
    float m = fmaxf(x, ALPHA * x);
    g_E1[i] = expf(x - m);
    g_E2[i] = expf(ALPHA * x - m);
    float y = g_s2[i] - s2m;
    g_F1[i] = expf(y);
    g_F2[i] = expf(ALPHA * y);
}

// ---------------- kernel 4: mma.sync tf32 attention --------------------------
// CTA: 128 rows (i), 1024-wide j slice. 4 warps, warp w owns rows [w*32, w*32+32).
__global__ __launch_bounds__(128, 4) void k_attn_mma(const int* __restrict__ adj) {
    __shared__ float E1s[TI], E2s[TI];
    __shared__ float F1s[JSLICE], F2s[JSLICE];     // 8 KB
    __shared__ float w_s[TI][36];                  // 18 KB (tf32 bits)
    __shared__ float wh_s[KT][68];                 // 8.5 KB (tf32 bits)

    int tid  = threadIdx.x;
    int lane = tid & 31;
    int wid  = tid >> 5;
    int tile  = blockIdx.x >> 3;
    int slice = blockIdx.x & (S_SLICES - 1);
    int i0 = tile * TI;
    int j0 = slice * JSLICE;

    E1s[tid] = g_E1[i0 + tid];
    E2s[tid] = g_E2[i0 + tid];
#pragma unroll
    for (int q = 0; q < JSLICE / 128; q++) {
        F1s[tid + q * 128] = g_F1[j0 + tid + q * 128];
        F2s[tid + q * 128] = g_F2[j0 + tid + q * 128];
    }
    __syncthreads();

    int wbase = wid * 32;
    int a_ = lane >> 3;        // row offset within 4-row pass group
    int b_ = lane & 7;         // col group (4 j's)
    int g  = lane >> 2;        // mma group id
    int t  = lane & 3;         // mma thread-in-group

    const int* adjp = adj + (size_t)i0 * N + j0;

    float den[8];
#pragma unroll
    for (int p = 0; p < 8; p++) den[p] = 0.f;
    float acc[2][8][4];
#pragma unroll
    for (int mt = 0; mt < 2; mt++)
#pragma unroll
        for (int n = 0; n < 8; n++)
#pragma unroll
            for (int c = 0; c < 4; c++) acc[mt][n][c] = 0.f;

    for (int jt = 0; jt < JSLICE; jt += KT) {
        // ---- weights: warp covers its 32 rows x 32 j's, coalesced adj ----
        float4 f1 = *(float4*)&F1s[jt + b_ * 4];
        float4 f2 = *(float4*)&F2s[jt + b_ * 4];
#pragma unroll 4
        for (int p = 0; p < 8; p++) {
            int r = wbase + p * 4 + a_;
            int4 av = *(const int4*)&adjp[(size_t)r * N + jt + b_ * 4];
            float e1 = E1s[r], e2 = E2s[r];
            float w0 = (av.x > 0) ? fmaxf(e1 * f1.x, e2 * f2.x) : 0.f;
            float w1 = (av.y > 0) ? fmaxf(e1 * f1.y, e2 * f2.y) : 0.f;
            float w2 = (av.z > 0) ? fmaxf(e1 * f1.z, e2 * f2.z) : 0.f;
            float w3 = (av.w > 0) ? fmaxf(e1 * f1.w, e2 * f2.w) : 0.f;
            uint4 wv;
            wv.x = cvt_tf32(w0); wv.y = cvt_tf32(w1);
            wv.z = cvt_tf32(w2); wv.w = cvt_tf32(w3);
            den[p] += (__uint_as_float(wv.x) + __uint_as_float(wv.y))
                    + (__uint_as_float(wv.z) + __uint_as_float(wv.w));
            *(uint4*)&w_s[r][b_ * 4] = wv;
        }
        // ---- Wh tile [32 x 64] -> tf32 smem ----
#pragma unroll
        for (int q = 0; q < 4; q++) {
            int lin = tid + q * 128;
            int j = lin >> 4, f = (lin & 15) << 2;
            float4 v = *(const float4*)&g_Wh[(size_t)(j0 + jt + j) * FOUT + f];
            uint4 c;
            c.x = cvt_tf32(v.x); c.y = cvt_tf32(v.y);
            c.z = cvt_tf32(v.z); c.w = cvt_tf32(v.w);
            *(uint4*)&wh_s[j][f] = c;
        }
        __syncthreads();

        // ---- mma phase: 4 k8-steps x 2 m16 x 8 n8 ----
#pragma unroll
        for (int k = 0; k < 4; k++) {
            int k0 = k * 8;
            uint32_t bfr[8][2];
#pragma unroll
            for (int n = 0; n < 8; n++) {
                bfr[n][0] = __float_as_uint(wh_s[k0 + t][n * 8 + g]);
                bfr[n][1] = __float_as_uint(wh_s[k0 + t + 4][n * 8 + g]);
            }
#pragma unroll
            for (int mt = 0; mt < 2; mt++) {
                int r0 = wbase + mt * 16 + g;
                uint32_t afr[4];
                afr[0] = __float_as_uint(w_s[r0][k0 + t]);
                afr[1] = __float_as_uint(w_s[r0 + 8][k0 + t]);
                afr[2] = __float_as_uint(w_s[r0][k0 + t + 4]);
                afr[3] = __float_as_uint(w_s[r0 + 8][k0 + t + 4]);
#pragma unroll
                for (int n = 0; n < 8; n++) mma8(acc[mt][n], afr, bfr[n]);
            }
        }
        __syncthreads();
    }

    // ---- denominator: reduce across 8 lanes sharing each row ----
#pragma unroll
    for (int p = 0; p < 8; p++) {
        den[p] += __shfl_down_sync(0xffffffffu, den[p], 4, 8);
        den[p] += __shfl_down_sync(0xffffffffu, den[p], 2, 8);
        den[p] += __shfl_down_sync(0xffffffffu, den[p], 1, 8);
    }
    if (b_ == 0) {
#pragma unroll
        for (int p = 0; p < 8; p++)
            g_pden[(size_t)slice * N + i0 + wbase + p * 4 + a_] = den[p];
    }

    // ---- numerator partials ----
#pragma unroll
    for (int mt = 0; mt < 2; mt++) {
#pragma unroll
        for (int n = 0; n < 8; n++) {
            int r0 = wbase + mt * 16 + g;
            size_t base = ((size_t)slice * N + i0 + r0) * FOUT + n * 8 + 2 * t;
            *(float2*)&g_pnum[base] = make_float2(acc[mt][n][0], acc[mt][n][1]);
            *(float2*)&g_pnum[base + 8 * FOUT] = make_float2(acc[mt][n][2], acc[mt][n][3]);
        }
    }
}

// ---------------- kernel 5: combine slices, normalize, elu ------------------
__global__ __launch_bounds__(256) void k_reduce(float* __restrict__ out) {
    int t = blockIdx.x * blockDim.x + threadIdx.x;
    if (t >= N * FOUT / 4) return;
    int i = t >> 4, c4 = (t & 15) << 2;
    float sx = 0.f, sy = 0.f, sz = 0.f, sw = 0.f, d = 0.f;
#pragma unroll
    for (int s = 0; s < S_SLICES; s++) {
        float4 v = *(const float4*)&g_pnum[((size_t)s * N + i) * FOUT + c4];
        sx += v.x; sy += v.y; sz += v.z; sw += v.w;
        d  += g_pden[(size_t)s * N + i];
    }
    float inv = 1.f / d;
    float ox = sx * inv, oy = sy * inv, oz = sz * inv, ow = sw * inv;
    float4 o;
    o.x = ox > 0.f ? ox : expm1f(ox);
    o.y = oy > 0.f ? oy : expm1f(oy);
    o.z = oz > 0.f ? oz : expm1f(oz);
    o.w = ow > 0.f ? ow : expm1f(ow);
    *(float4*)&out[(size_t)i * FOUT + c4] = o;
}

// ---------------------------------------------------------------------------
extern "C" void kernel_launch(void* const* d_in, const int* in_sizes, int n_in,
                              void* d_out, int out_size) {
    const float* h   = (const float*)d_in[0];
    const float* W   = (const float*)d_in[1];
    const float* a   = (const float*)d_in[2];
    const int*   adj = (const int*)d_in[3];
    float* out = (float*)d_out;

    k_gemm<<<N / GTI, 256>>>(h, W);
    k_s12<<<N / 8, 256>>>(a);
    k_max<<<1, 256>>>();
    k_factors<<<N / 256, 256>>>();
    k_attn_mma<<<(N / TI) * S_SLICES, 128>>>(adj);
    k_reduce<<<(N * FOUT / 4) / 256, 256>>>(out);
}

// round 9
// speedup vs baseline: 2.3799x; 1.2537x over previous
#include <cuda_runtime.h>
#include <math.h>
#include <stdint.h>

#define N     8192
#define FIN   512
#define FOUT  64
#define ALPHA 0.2f

#define S_SLICES 4
#define TI       128
#define KT       32
#define JSLICE   (N / S_SLICES)   // 2048
#define NITER    (JSLICE / KT)    // 64

// ---------------- device scratch ------------------------------------------
__device__ float g_Wh[N * FOUT];                 // 2 MB
__device__ float g_s1[N];
__device__ float g_s2[N];
__device__ float g_s2max;
__device__ float g_E1[N], g_E2[N], g_F1[N], g_F2[N];
__device__ float g_pnum[S_SLICES * N * FOUT];    // 8.4 MB
__device__ float g_pden[S_SLICES * N];

__forceinline__ __device__ uint32_t cvt_tf32(float f) {
    uint32_t u; asm("cvt.rna.tf32.f32 %0, %1;" : "=r"(u) : "f"(f)); return u;
}

__forceinline__ __device__ void mma8(float* d, const uint32_t* a, const uint32_t* b) {
    asm volatile(
        "mma.sync.aligned.m16n8k8.row.col.f32.tf32.tf32.f32 "
        "{%0,%1,%2,%3}, {%4,%5,%6,%7}, {%8,%9}, {%0,%1,%2,%3};"
        : "+f"(d[0]), "+f"(d[1]), "+f"(d[2]), "+f"(d[3])
        : "r"(a[0]), "r"(a[1]), "r"(a[2]), "r"(a[3]), "r"(b[0]), "r"(b[1]));
}

// ---------------- kernel 1: Wh = h @ W --------------------------------------
#define GTI 64
#define GKC 64
__global__ __launch_bounds__(256) void k_gemm(const float* __restrict__ h,
                                              const float* __restrict__ W) {
    __shared__ float hs[GKC][GTI + 4];
    __shared__ float Ws[GKC][FOUT];
    int i0 = blockIdx.x * GTI, tid = threadIdx.x;
    int ig = tid >> 4, fg = tid & 15;
    float acc[4][4];
#pragma unroll
    for (int r = 0; r < 4; r++)
#pragma unroll
        for (int c = 0; c < 4; c++) acc[r][c] = 0.f;
    for (int k0 = 0; k0 < FIN; k0 += GKC) {
#pragma unroll
        for (int q = 0; q < 4; q++) {
            int lin = tid + q * 256, ii = lin >> 4, kq = (lin & 15) << 2;
            float4 v = *(const float4*)&h[(size_t)(i0 + ii) * FIN + k0 + kq];
            hs[kq + 0][ii] = v.x; hs[kq + 1][ii] = v.y;
            hs[kq + 2][ii] = v.z; hs[kq + 3][ii] = v.w;
        }
#pragma unroll
        for (int q = 0; q < 4; q++) {
            int lin = tid + q * 256, kk = lin >> 4, fq = (lin & 15) << 2;
            *(float4*)&Ws[kk][fq] = *(const float4*)&W[(size_t)(k0 + kk) * FOUT + fq];
        }
        __syncthreads();
#pragma unroll
        for (int kk = 0; kk < GKC; kk++) {
            float4 av = *(float4*)&hs[kk][ig * 4];
            float4 bv = *(float4*)&Ws[kk][fg * 4];
            float ar[4] = {av.x, av.y, av.z, av.w};
            float br[4] = {bv.x, bv.y, bv.z, bv.w};
#pragma unroll
            for (int r = 0; r < 4; r++)
#pragma unroll
                for (int c = 0; c < 4; c++) acc[r][c] += ar[r] * br[c];
        }
        __syncthreads();
    }
#pragma unroll
    for (int r = 0; r < 4; r++)
        *(float4*)&g_Wh[(size_t)(i0 + ig * 4 + r) * FOUT + fg * 4] =
            make_float4(acc[r][0], acc[r][1], acc[r][2], acc[r][3]);
}

// ---------------- kernel 2: s1 = Wh@a1, s2 = Wh@a2 --------------------------
__global__ __launch_bounds__(256) void k_s12(const float* __restrict__ a) {
    int warp = (blockIdx.x * blockDim.x + threadIdx.x) >> 5;
    int lane = threadIdx.x & 31;
    if (warp >= N) return;
    const float* whr = g_Wh + (size_t)warp * FOUT;
    float v0 = whr[lane], v1 = whr[lane + 32];
    float p1 = v0 * a[lane]      + v1 * a[lane + 32];
    float p2 = v0 * a[64 + lane] + v1 * a[96 + lane];
#pragma unroll
    for (int off = 16; off > 0; off >>= 1) {
        p1 += __shfl_down_sync(0xffffffffu, p1, off);
        p2 += __shfl_down_sync(0xffffffffu, p2, off);
    }
    if (lane == 0) { g_s1[warp] = p1; g_s2[warp] = p2; }
}

// ---------------- kernel 3: global max of s2 --------------------------------
__global__ __launch_bounds__(256) void k_max() {
    __shared__ float sm[256];
    int tid = threadIdx.x;
    float m = -INFINITY;
    for (int i = tid; i < N; i += 256) m = fmaxf(m, g_s2[i]);
    sm[tid] = m;
    __syncthreads();
#pragma unroll
    for (int s = 128; s > 0; s >>= 1) {
        if (tid < s) sm[tid] = fmaxf(sm[tid], sm[tid + s]);
        __syncthreads();
    }
    if (tid == 0) g_s2max = sm[0];
}

// ---------------- kernel 3b: per-node softmax factors -----------------------
// exp(lrelu(s1_i+s2_j) - m_i) == max(E1_i*F1_j, E2_i*F2_j); all exponents <= 0.
__global__ __launch_bounds__(256) void k_factors() {
    int i = blockIdx.x * 256 + threadIdx.x;
    float s2m = g_s2max;
    float x = g_s1[i] + s2m;
    float m = fmaxf(x, ALPHA * x);
    g_E1[i] = expf(x - m);
    g_E2[i] = expf(ALPHA * x - m);
    float y = g_s2[i] - s2m;
    g_F1[i] = expf(y);
    g_F2[i] = expf(ALPHA * y);
}

// ---------------- kernel 4: mma.sync tf32 attention --------------------------
// CTA: 256 threads / 8 warps, 128 rows (i), 2048-wide j slice.
// w-phase: warp w owns rows [w*16, w*16+16).
// mma-phase: warps pair up — rowgroup (w>>1)*32, n-half (w&1).
__global__ __launch_bounds__(256, 2) void k_attn_mma(const int* __restrict__ adj) {
    __shared__ float E1s[TI], E2s[TI];
    __shared__ float F1s[JSLICE], F2s[JSLICE];     // 16 KB
    __shared__ float w_s[TI][36];                  // 18 KB (tf32 bits)
    __shared__ float wh_s[KT][72];                 // 9 KB (tf32 bits)

    int tid  = threadIdx.x;
    int lane = tid & 31;
    int wid  = tid >> 5;
    int tile  = blockIdx.x >> 2;
    int slice = blockIdx.x & (S_SLICES - 1);
    int i0 = tile * TI;
    int j0 = slice * JSLICE;

    if (tid < TI) {
        E1s[tid] = g_E1[i0 + tid];
        E2s[tid] = g_E2[i0 + tid];
    }
#pragma unroll
    for (int q = 0; q < JSLICE / 256; q++) {
        F1s[tid + q * 256] = g_F1[j0 + tid + q * 256];
        F2s[tid + q * 256] = g_F2[j0 + tid + q * 256];
    }
    __syncthreads();

    int a_ = lane >> 3;        // 0..3: row offset
    int b_ = lane & 7;         // 0..7: 4-j column group
    int g  = lane >> 2;        // mma group id
    int t  = lane & 3;         // mma thread-in-group

    int rbase = wid * 16;                 // w-phase rows
    int mgrp  = (wid >> 1) * 32;          // mma rowgroup
    int nh    = (wid & 1) * 4;            // mma n-half (4 n8-tiles)

    const int* adjp = adj + (size_t)i0 * N + j0;

    float den[4];
#pragma unroll
    for (int p = 0; p < 4; p++) den[p] = 0.f;
    float acc[2][4][4];
#pragma unroll
    for (int mt = 0; mt < 2; mt++)
#pragma unroll
        for (int n = 0; n < 4; n++)
#pragma unroll
            for (int c = 0; c < 4; c++) acc[mt][n][c] = 0.f;

    // prefetch adj tile 0
    int4 av[4];
#pragma unroll
    for (int p = 0; p < 4; p++)
        av[p] = *(const int4*)&adjp[(size_t)(rbase + p * 4 + a_) * N + b_ * 4];

    for (int jt = 0; jt < JSLICE; jt += KT) {
        // ---- weights from prefetched adj ----
        float4 f1 = *(float4*)&F1s[jt + b_ * 4];
        float4 f2 = *(float4*)&F2s[jt + b_ * 4];
#pragma unroll
        for (int p = 0; p < 4; p++) {
            int r = rbase + p * 4 + a_;
            float e1 = E1s[r], e2 = E2s[r];
            float w0 = (av[p].x > 0) ? fmaxf(e1 * f1.x, e2 * f2.x) : 0.f;
            float w1 = (av[p].y > 0) ? fmaxf(e1 * f1.y, e2 * f2.y) : 0.f;
            float w2 = (av[p].z > 0) ? fmaxf(e1 * f1.z, e2 * f2.z) : 0.f;
            float w3 = (av[p].w > 0) ? fmaxf(e1 * f1.w, e2 * f2.w) : 0.f;
            uint4 wv;
            wv.x = cvt_tf32(w0); wv.y = cvt_tf32(w1);
            wv.z = cvt_tf32(w2); wv.w = cvt_tf32(w3);
            den[p] += (__uint_as_float(wv.x) + __uint_as_float(wv.y))
                    + (__uint_as_float(wv.z) + __uint_as_float(wv.w));
            *(uint4*)&w_s[r][b_ * 4] = wv;
        }
        // ---- Wh tile [32 x 64] -> tf32 smem ----
#pragma unroll
        for (int q = 0; q < 2; q++) {
            int lin = tid + q * 256;
            int j = lin >> 4, f = (lin & 15) << 2;
            float4 v = *(const float4*)&g_Wh[(size_t)(j0 + jt + j) * FOUT + f];
            uint4 c;
            c.x = cvt_tf32(v.x); c.y = cvt_tf32(v.y);
            c.z = cvt_tf32(v.z); c.w = cvt_tf32(v.w);
            *(uint4*)&wh_s[j][f] = c;
        }
        // ---- prefetch next adj tile (covers latency over mma phase) ----
        if (jt + KT < JSLICE) {
#pragma unroll
            for (int p = 0; p < 4; p++)
                av[p] = *(const int4*)&adjp[(size_t)(rbase + p * 4 + a_) * N
                                            + jt + KT + b_ * 4];
        }
        __syncthreads();

        // ---- mma phase: 4 k8-steps x 2 m16 x 4 n8 (this warp's n-half) ----
#pragma unroll
        for (int k = 0; k < 4; k++) {
            int k0 = k * 8;
            uint32_t bfr[4][2];
#pragma unroll
            for (int n = 0; n < 4; n++) {
                bfr[n][0] = __float_as_uint(wh_s[k0 + t][(nh + n) * 8 + g]);
                bfr[n][1] = __float_as_uint(wh_s[k0 + t + 4][(nh + n) * 8 + g]);
            }
#pragma unroll
            for (int mt = 0; mt < 2; mt++) {
                int r0 = mgrp + mt * 16 + g;
                uint32_t afr[4];
                afr[0] = __float_as_uint(w_s[r0][k0 + t]);
                afr[1] = __float_as_uint(w_s[r0 + 8][k0 + t]);
                afr[2] = __float_as_uint(w_s[r0][k0 + t + 4]);
                afr[3] = __float_as_uint(w_s[r0 + 8][k0 + t + 4]);
#pragma unroll
                for (int n = 0; n < 4; n++) mma8(acc[mt][n], afr, bfr[n]);
            }
        }
        __syncthreads();
    }

    // ---- denominator: reduce across 8 lanes sharing each row ----
#pragma unroll
    for (int p = 0; p < 4; p++) {
        den[p] += __shfl_down_sync(0xffffffffu, den[p], 4, 8);
        den[p] += __shfl_down_sync(0xffffffffu, den[p], 2, 8);
        den[p] += __shfl_down_sync(0xffffffffu, den[p], 1, 8);
    }
    if (b_ == 0) {
#pragma unroll
        for (int p = 0; p < 4; p++)
            g_pden[(size_t)slice * N + i0 + rbase + p * 4 + a_] = den[p];
    }

    // ---- numerator partials ----
#pragma unroll
    for (int mt = 0; mt < 2; mt++) {
#pragma unroll
        for (int n = 0; n < 4; n++) {
            int r0 = mgrp + mt * 16 + g;
            size_t base = ((size_t)slice * N + i0 + r0) * FOUT + (nh + n) * 8 + 2 * t;
            *(float2*)&g_pnum[base] = make_float2(acc[mt][n][0], acc[mt][n][1]);
            *(float2*)&g_pnum[base + 8 * FOUT] = make_float2(acc[mt][n][2], acc[mt][n][3]);
        }
    }
}

// ---------------- kernel 5: combine slices, normalize, elu ------------------
__global__ __launch_bounds__(256) void k_reduce(float* __restrict__ out) {
    int t = blockIdx.x * blockDim.x + threadIdx.x;
    if (t >= N * FOUT / 4) return;
    int i = t >> 4, c4 = (t & 15) << 2;
    float sx = 0.f, sy = 0.f, sz = 0.f, sw = 0.f, d = 0.f;
#pragma unroll
    for (int s = 0; s < S_SLICES; s++) {
        float4 v = *(const float4*)&g_pnum[((size_t)s * N + i) * FOUT + c4];
        sx += v.x; sy += v.y; sz += v.z; sw += v.w;
        d  += g_pden[(size_t)s * N + i];
    }
    float inv = 1.f / d;
    float ox = sx * inv, oy = sy * inv, oz = sz * inv, ow = sw * inv;
    float4 o;
    o.x = ox > 0.f ? ox : expm1f(ox);
    o.y = oy > 0.f ? oy : expm1f(oy);
    o.z = oz > 0.f ? oz : expm1f(oz);
    o.w = ow > 0.f ? ow : expm1f(ow);
    *(float4*)&out[(size_t)i * FOUT + c4] = o;
}

// ---------------------------------------------------------------------------
extern "C" void kernel_launch(void* const* d_in, const int* in_sizes, int n_in,
                              void* d_out, int out_size) {
    const float* h   = (const float*)d_in[0];
    const float* W   = (const float*)d_in[1];
    const float* a   = (const float*)d_in[2];
    const int*   adj = (const int*)d_in[3];
    float* out = (float*)d_out;

    k_gemm<<<N / GTI, 256>>>(h, W);
    k_s12<<<N / 8, 256>>>(a);
    k_max<<<1, 256>>>();
    k_factors<<<N / 256, 256>>>();
    k_attn_mma<<<(N / TI) * S_SLICES, 256>>>(adj);
    k_reduce<<<(N * FOUT / 4) / 256, 256>>>(out);
}

// round 11
// speedup vs baseline: 2.6332x; 1.1064x over previous
#include <cuda_runtime.h>
#include <math.h>
#include <stdint.h>

#define N     8192
#define FIN   512
#define FOUT  64
#define ALPHA 0.2f

#define S_SLICES 4
#define TI       128
#define KT       32
#define JSLICE   (N / S_SLICES)   // 2048
#define NITER    (JSLICE / KT)    // 64

#define W_STR   36
#define WH_STR  72
#define W_BUF   (TI * W_STR)      // 4608 floats
#define WH_BUF  (KT * WH_STR)     // 2304 floats
// dyn smem: E1[128] E2[128] F1[2048] F2[2048] w[2][4608] wh[2][2304]
#define SMEM_FLOATS (256 + 2 * JSLICE + 2 * W_BUF + 2 * WH_BUF)
#define SMEM_BYTES  (SMEM_FLOATS * 4)

// ---------------- device scratch ------------------------------------------
__device__ float g_Wh[N * FOUT];                 // 2 MB
__device__ float g_s1[N];
__device__ float g_s2[N];
__device__ float g_s2max;
__device__ float g_E1[N], g_E2[N], g_F1[N], g_F2[N];
__device__ float g_pnum[S_SLICES * N * FOUT];    // 8.4 MB
__device__ float g_pden[S_SLICES * N];

__forceinline__ __device__ uint32_t cvt_tf32(float f) {
    uint32_t u; asm("cvt.rna.tf32.f32 %0, %1;" : "=r"(u) : "f"(f)); return u;
}

__forceinline__ __device__ void mma8(float* d, const uint32_t* a, const uint32_t* b) {
    asm volatile(
        "mma.sync.aligned.m16n8k8.row.col.f32.tf32.tf32.f32 "
        "{%0,%1,%2,%3}, {%4,%5,%6,%7}, {%8,%9}, {%0,%1,%2,%3};"
        : "+f"(d[0]), "+f"(d[1]), "+f"(d[2]), "+f"(d[3])
        : "r"(a[0]), "r"(a[1]), "r"(a[2]), "r"(a[3]), "r"(b[0]), "r"(b[1]));
}

// ---------------- kernel 1: Wh = h @ W --------------------------------------
#define GTI 64
#define GKC 64
__global__ __launch_bounds__(256) void k_gemm(const float* __restrict__ h,
                                              const float* __restrict__ W) {
    __shared__ float hs[GKC][GTI + 4];
    __shared__ float Ws[GKC][FOUT];
    int i0 = blockIdx.x * GTI, tid = threadIdx.x;
    int ig = tid >> 4, fg = tid & 15;
    float acc[4][4];
#pragma unroll
    for (int r = 0; r < 4; r++)
#pragma unroll
        for (int c = 0; c < 4; c++) acc[r][c] = 0.f;
    for (int k0 = 0; k0 < FIN; k0 += GKC) {
#pragma unroll
        for (int q = 0; q < 4; q++) {
            int lin = tid + q * 256, ii = lin >> 4, kq = (lin & 15) << 2;
            float4 v = *(const float4*)&h[(size_t)(i0 + ii) * FIN + k0 + kq];
            hs[kq + 0][ii] = v.x; hs[kq + 1][ii] = v.y;
            hs[kq + 2][ii] = v.z; hs[kq + 3][ii] = v.w;
        }
#pragma unroll
        for (int q = 0; q < 4; q++) {
            int lin = tid + q * 256, kk = lin >> 4, fq = (lin & 15) << 2;
            *(float4*)&Ws[kk][fq] = *(const float4*)&W[(size_t)(k0 + kk) * FOUT + fq];
        }
        __syncthreads();
#pragma unroll
        for (int kk = 0; kk < GKC; kk++) {
            float4 av = *(float4*)&hs[kk][ig * 4];
            float4 bv = *(float4*)&Ws[kk][fg * 4];
            float ar[4] = {av.x, av.y, av.z, av.w};
            float br[4] = {bv.x, bv.y, bv.z, bv.w};
#pragma unroll
            for (int r = 0; r < 4; r++)
#pragma unroll
                for (int c = 0; c < 4; c++) acc[r][c] += ar[r] * br[c];
        }
        __syncthreads();
    }
#pragma unroll
    for (int r = 0; r < 4; r++)
        *(float4*)&g_Wh[(size_t)(i0 + ig * 4 + r) * FOUT + fg * 4] =
            make_float4(acc[r][0], acc[r][1], acc[r][2], acc[r][3]);
}

// ---------------- kernel 2: s1 = Wh@a1, s2 = Wh@a2 --------------------------
__global__ __launch_bounds__(256) void k_s12(const float* __restrict__ a) {
    int warp = (blockIdx.x * blockDim.x + threadIdx.x) >> 5;
    int lane = threadIdx.x & 31;
    if (warp >= N) return;
    const float* whr = g_Wh + (size_t)warp * FOUT;
    float v0 = whr[lane], v1 = whr[lane + 32];
    float p1 = v0 * a[lane]      + v1 * a[lane + 32];
    float p2 = v0 * a[64 + lane] + v1 * a[96 + lane];
#pragma unroll
    for (int off = 16; off > 0; off >>= 1) {
        p1 += __shfl_down_sync(0xffffffffu, p1, off);
        p2 += __shfl_down_sync(0xffffffffu, p2, off);
    }
    if (lane == 0) { g_s1[warp] = p1; g_s2[warp] = p2; }
}

// ---------------- kernel 3: global max of s2 --------------------------------
__global__ __launch_bounds__(256) void k_max() {
    __shared__ float sm[256];
    int tid = threadIdx.x;
    float m = -INFINITY;
    for (int i = tid; i < N; i += 256) m = fmaxf(m, g_s2[i]);
    sm[tid] = m;
    __syncthreads();
#pragma unroll
    for (int s = 128; s > 0; s >>= 1) {
        if (tid < s) sm[tid] = fmaxf(sm[tid], sm[tid + s]);
        __syncthreads();
    }
    if (tid == 0) g_s2max = sm[0];
}

// ---------------- kernel 3b: per-node softmax factors -----------------------
// exp(lrelu(s1_i+s2_j) - m_i) == max(E1_i*F1_j, E2_i*F2_j); all exponents <= 0.
__global__ __launch_bounds__(256) void k_factors() {
    int i = blockIdx.x * 256 + threadIdx.x;
    float s2m = g_s2max;
    float x = g_s1[i] + s2m;
    float m = fmaxf(x, ALPHA * x);
    g_E1[i] = expf(x - m);
    g_E2[i] = expf(ALPHA * x - m);
    float y = g_s2[i] - s2m;
    g_F1[i] = expf(y);
    g_F2[i] = expf(ALPHA * y);
}

// ---------------- produce: weights + wh tile -> smem buffer -----------------
__device__ __forceinline__ void produce_tile(
    float* __restrict__ wp, float* __restrict__ whp,
    const int4* av, const float4* whv,
    const float* __restrict__ E1s, const float* __restrict__ E2s,
    const float* __restrict__ F1s, const float* __restrict__ F2s,
    int jt, int rbase, int a_, int b_, int tid, float* den)
{
    float4 f1 = *(const float4*)&F1s[jt + b_ * 4];
    float4 f2 = *(const float4*)&F2s[jt + b_ * 4];
#pragma unroll
    for (int p = 0; p < 4; p++) {
        int r = rbase + p * 4 + a_;
        float e1 = E1s[r], e2 = E2s[r];
        float w0 = (av[p].x > 0) ? fmaxf(e1 * f1.x, e2 * f2.x) : 0.f;
        float w1 = (av[p].y > 0) ? fmaxf(e1 * f1.y, e2 * f2.y) : 0.f;
        float w2 = (av[p].z > 0) ? fmaxf(e1 * f1.z, e2 * f2.z) : 0.f;
        float w3 = (av[p].w > 0) ? fmaxf(e1 * f1.w, e2 * f2.w) : 0.f;
        uint4 wv;
        wv.x = cvt_tf32(w0); wv.y = cvt_tf32(w1);
        wv.z = cvt_tf32(w2); wv.w = cvt_tf32(w3);
        den[p] += (__uint_as_float(wv.x) + __uint_as_float(wv.y))
                + (__uint_as_float(wv.z) + __uint_as_float(wv.w));
        *(uint4*)&wp[r * W_STR + b_ * 4] = wv;
    }
#pragma unroll
    for (int q = 0; q < 2; q++) {
        int lin = tid + q * 256;
        int j = lin >> 4, f = (lin & 15) << 2;
        uint4 c;
        c.x = cvt_tf32(whv[q].x); c.y = cvt_tf32(whv[q].y);
        c.z = cvt_tf32(whv[q].z); c.w = cvt_tf32(whv[q].w);
        *(uint4*)&whp[j * WH_STR + f] = c;
    }
}

// ---------------- kernel 4: pipelined mma.sync tf32 attention ---------------
__global__ __launch_bounds__(256, 2) void k_attn_mma(const int* __restrict__ adj) {
    extern __shared__ float dyn[];
    float* E1s  = dyn;
    float* E2s  = dyn + 128;
    float* F1s  = dyn + 256;
    float* F2s  = dyn + 256 + JSLICE;
    float* w_sm = dyn + 256 + 2 * JSLICE;
    float* wh_sm = w_sm + 2 * W_BUF;

    int tid  = threadIdx.x;
    int lane = tid & 31;
    int wid  = tid >> 5;
    int tile  = blockIdx.x >> 2;
    int slice = blockIdx.x & (S_SLICES - 1);
    int i0 = tile * TI;
    int j0 = slice * JSLICE;

    if (tid < TI) {
        E1s[tid] = g_E1[i0 + tid];
        E2s[tid] = g_E2[i0 + tid];
    }
#pragma unroll
    for (int q = 0; q < JSLICE / 256; q++) {
        F1s[tid + q * 256] = g_F1[j0 + tid + q * 256];
        F2s[tid + q * 256] = g_F2[j0 + tid + q * 256];
    }

    int a_ = lane >> 3;        // 0..3: row offset
    int b_ = lane & 7;         // 0..7: 4-j column group
    int g  = lane >> 2;        // mma group id
    int t  = lane & 3;         // mma thread-in-group

    int rbase = wid * 16;                 // w-phase rows
    int mgrp  = (wid >> 1) * 32;          // mma rowgroup
    int nh    = (wid & 1) * 4;            // mma n-half (4 n8-tiles)

    // per-thread adj row pointers (fixed rows across all iterations)
    const int* rp[4];
#pragma unroll
    for (int p = 0; p < 4; p++)
        rp[p] = adj + (size_t)(i0 + rbase + p * 4 + a_) * N + j0;
    // per-thread Wh load pointers
    const float* whq[2];
#pragma unroll
    for (int q = 0; q < 2; q++) {
        int lin = tid + q * 256;
        whq[q] = g_Wh + (size_t)(j0 + (lin >> 4)) * FOUT + ((lin & 15) << 2);
    }

    float den[4];
#pragma unroll
    for (int p = 0; p < 4; p++) den[p] = 0.f;
    float acc[2][4][4];
#pragma unroll
    for (int mt = 0; mt < 2; mt++)
#pragma unroll
        for (int n = 0; n < 4; n++)
#pragma unroll
            for (int c = 0; c < 4; c++) acc[mt][n][c] = 0.f;

    // ---- preamble: load + produce tile 0, issue loads for tile 1 ----
    int4 av[4];
    float4 whv[2];
#pragma unroll
    for (int p = 0; p < 4; p++) av[p] = *(const int4*)&rp[p][b_ * 4];
#pragma unroll
    for (int q = 0; q < 2; q++) whv[q] = *(const float4*)whq[q];
    __syncthreads();   // E/F tiles ready
    produce_tile(w_sm, wh_sm, av, whv, E1s, E2s, F1s, F2s, 0,
                 rbase, a_, b_, tid, den);
#pragma unroll
    for (int p = 0; p < 4; p++) av[p] = *(const int4*)&rp[p][KT + b_ * 4];
#pragma unroll
    for (int q = 0; q < 2; q++)
        whv[q] = *(const float4*)(whq[q] + (size_t)KT * FOUT);
    __syncthreads();   // buf0 published

    for (int it = 0; it < NITER; it++) {
        const float* wp  = w_sm  + (it & 1) * W_BUF;
        const float* whp = wh_sm + (it & 1) * WH_BUF;

        // ---- mma phase: consume buf[it&1] ----
#pragma unroll
        for (int k = 0; k < 4; k++) {
            int k0 = k * 8;
            uint32_t bfr[4][2];
#pragma unroll
            for (int n = 0; n < 4; n++) {
                bfr[n][0] = __float_as_uint(whp[(k0 + t) * WH_STR + (nh + n) * 8 + g]);
                bfr[n][1] = __float_as_uint(whp[(k0 + t + 4) * WH_STR + (nh + n) * 8 + g]);
            }
#pragma unroll
            for (int mt = 0; mt < 2; mt++) {
                int r0 = mgrp + mt * 16 + g;
                uint32_t afr[4];
                afr[0] = __float_as_uint(wp[r0 * W_STR + k0 + t]);
                afr[1] = __float_as_uint(wp[(r0 + 8) * W_STR + k0 + t]);
                afr[2] = __float_as_uint(wp[r0 * W_STR + k0 + t + 4]);
                afr[3] = __float_as_uint(wp[(r0 + 8) * W_STR + k0 + t + 4]);
#pragma unroll
                for (int n = 0; n < 4; n++) mma8(acc[mt][n], afr, bfr[n]);
            }
        }

        // ---- produce tile it+1 into the other buffer, then prefetch it+2 ----
        if (it + 1 < NITER) {
            produce_tile(w_sm + ((it + 1) & 1) * W_BUF,
                         wh_sm + ((it + 1) & 1) * WH_BUF,
                         av, whv, E1s, E2s, F1s, F2s, (it + 1) * KT,
                         rbase, a_, b_, tid, den);
            if (it + 2 < NITER) {
                int jn = (it + 2) * KT;
#pragma unroll
                for (int p = 0; p < 4; p++)
                    av[p] = *(const int4*)&rp[p][jn + b_ * 4];
#pragma unroll
                for (int q = 0; q < 2; q++)
                    whv[q] = *(const float4*)(whq[q] + (size_t)jn * FOUT);
            }
        }
        __syncthreads();
    }

    // ---- denominator: reduce across 8 lanes sharing each row ----
#pragma unroll
    for (int p = 0; p < 4; p++) {
        den[p] += __shfl_down_sync(0xffffffffu, den[p], 4, 8);
        den[p] += __shfl_down_sync(0xffffffffu, den[p], 2, 8);
        den[p] += __shfl_down_sync(0xffffffffu, den[p], 1, 8);
    }
    if (b_ == 0) {
#pragma unroll
        for (int p = 0; p < 4; p++)
            g_pden[(size_t)slice * N + i0 + rbase + p * 4 + a_] = den[p];
    }

    // ---- numerator partials ----
#pragma unroll
    for (int mt = 0; mt < 2; mt++) {
#pragma unroll
        for (int n = 0; n < 4; n++) {
            int r0 = mgrp + mt * 16 + g;
            size_t base = ((size_t)slice * N + i0 + r0) * FOUT + (nh + n) * 8 + 2 * t;
            *(float2*)&g_pnum[base] = make_float2(acc[mt][n][0], acc[mt][n][1]);
            *(float2*)&g_pnum[base + 8 * FOUT] = make_float2(acc[mt][n][2], acc[mt][n][3]);
        }
    }
}

// ---------------- kernel 5: combine slices, normalize, elu ------------------
__global__ __launch_bounds__(256) void k_reduce(float* __restrict__ out) {
    int t = blockIdx.x * blockDim.x + threadIdx.x;
    if (t >= N * FOUT / 4) return;
    int i = t >> 4, c4 = (t & 15) << 2;
    float sx = 0.f, sy = 0.f, sz = 0.f, sw = 0.f, d = 0.f;
#pragma unroll
    for (int s = 0; s < S_SLICES; s++) {
        float4 v = *(const float4*)&g_pnum[((size_t)s * N + i) * FOUT + c4];
        sx += v.x; sy += v.y; sz += v.z; sw += v.w;
        d  += g_pden[(size_t)s * N + i];
    }
    float inv = 1.f / d;
    float ox = sx * inv, oy = sy * inv, oz = sz * inv, ow = sw * inv;
    float4 o;
    o.x = ox > 0.f ? ox : expm1f(ox);
    o.y = oy > 0.f ? oy : expm1f(oy);
    o.z = oz > 0.f ? oz : expm1f(oz);
    o.w = ow > 0.f ? ow : expm1f(ow);
    *(float4*)&out[(size_t)i * FOUT + c4] = o;
}

// ---------------------------------------------------------------------------
extern "C" void kernel_launch(void* const* d_in, const int* in_sizes, int n_in,
                              void* d_out, int out_size) {
    const float* h   = (const float*)d_in[0];
    const float* W   = (const float*)d_in[1];
    const float* a   = (const float*)d_in[2];
    const int*   adj = (const int*)d_in[3];
    float* out = (float*)d_out;

    static int attr_set = 0;
    if (!attr_set) {
        cudaFuncSetAttribute(k_attn_mma,
                             cudaFuncAttributeMaxDynamicSharedMemorySize, SMEM_BYTES);
        attr_set = 1;
    }

    k_gemm<<<N / GTI, 256>>>(h, W);
    k_s12<<<N / 8, 256>>>(a);
    k_max<<<1, 256>>>();
    k_factors<<<N / 256, 256>>>();
    k_attn_mma<<<(N / TI) * S_SLICES, 256, SMEM_BYTES>>>(adj);
    k_reduce<<<(N * FOUT / 4) / 256, 256>>>(out);
}

// round 12
// speedup vs baseline: 3.1075x; 1.1801x over previous
#include <cuda_runtime.h>
#include <cuda_fp16.h>
#include <math.h>
#include <stdint.h>

#define N     8192
#define FIN   512
#define FOUT  64
#define ALPHA 0.2f

#define S_SLICES 4
#define TI       128
#define KT       32
#define JSLICE   (N / S_SLICES)   // 2048
#define NITER    (JSLICE / KT)    // 64

#define W16_STR 40                 // halves; 20 words -> bijective bank map
#define W_BUF   (TI * W16_STR)     // 5120 halves
#define WH_BUF  (FOUT * W16_STR)   // 2560 halves
// dyn smem: E1[128] E2[128] F1[2048] F2[2048] (f32) + w[2][5120] wh[2][2560] (f16)
#define SMEM_BYTES ((256 + 2 * JSLICE) * 4 + (2 * W_BUF + 2 * WH_BUF) * 2)

// ---------------- device scratch ------------------------------------------
__device__ float  g_Wh[N * FOUT];                 // 2 MB
__device__ __half g_WhT16[FOUT * N];              // 1 MB, [f][j] fp16
__device__ float  g_s1[N];
__device__ float  g_s2[N];
__device__ float  g_s2max;
__device__ float  g_E1[N], g_E2[N], g_F1[N], g_F2[N];
__device__ float  g_pnum[S_SLICES * N * FOUT];    // 8.4 MB
__device__ float  g_pden[S_SLICES * N];

__forceinline__ __device__ void mma16(float* d, const uint32_t* a, const uint32_t* b) {
    asm volatile(
        "mma.sync.aligned.m16n8k16.row.col.f32.f16.f16.f32 "
        "{%0,%1,%2,%3}, {%4,%5,%6,%7}, {%8,%9}, {%0,%1,%2,%3};"
        : "+f"(d[0]), "+f"(d[1]), "+f"(d[2]), "+f"(d[3])
        : "r"(a[0]), "r"(a[1]), "r"(a[2]), "r"(a[3]), "r"(b[0]), "r"(b[1]));
}

// ---------------- kernel 1: Wh = h @ W --------------------------------------
#define GTI 64
#define GKC 64
__global__ __launch_bounds__(256) void k_gemm(const float* __restrict__ h,
                                              const float* __restrict__ W) {
    __shared__ float hs[GKC][GTI + 4];
    __shared__ float Ws[GKC][FOUT];
    int i0 = blockIdx.x * GTI, tid = threadIdx.x;
    int ig = tid >> 4, fg = tid & 15;
    float acc[4][4];
#pragma unroll
    for (int r = 0; r < 4; r++)
#pragma unroll
        for (int c = 0; c < 4; c++) acc[r][c] = 0.f;
    for (int k0 = 0; k0 < FIN; k0 += GKC) {
#pragma unroll
        for (int q = 0; q < 4; q++) {
            int lin = tid + q * 256, ii = lin >> 4, kq = (lin & 15) << 2;
            float4 v = *(const float4*)&h[(size_t)(i0 + ii) * FIN + k0 + kq];
            hs[kq + 0][ii] = v.x; hs[kq + 1][ii] = v.y;
            hs[kq + 2][ii] = v.z; hs[kq + 3][ii] = v.w;
        }
#pragma unroll
        for (int q = 0; q < 4; q++) {
            int lin = tid + q * 256, kk = lin >> 4, fq = (lin & 15) << 2;
            *(float4*)&Ws[kk][fq] = *(const float4*)&W[(size_t)(k0 + kk) * FOUT + fq];
        }
        __syncthreads();
#pragma unroll
        for (int kk = 0; kk < GKC; kk++) {
            float4 av = *(float4*)&hs[kk][ig * 4];
            float4 bv = *(float4*)&Ws[kk][fg * 4];
            float ar[4] = {av.x, av.y, av.z, av.w};
            float br[4] = {bv.x, bv.y, bv.z, bv.w};
#pragma unroll
            for (int r = 0; r < 4; r++)
#pragma unroll
                for (int c = 0; c < 4; c++) acc[r][c] += ar[r] * br[c];
        }
        __syncthreads();
    }
#pragma unroll
    for (int r = 0; r < 4; r++)
        *(float4*)&g_Wh[(size_t)(i0 + ig * 4 + r) * FOUT + fg * 4] =
            make_float4(acc[r][0], acc[r][1], acc[r][2], acc[r][3]);
}

// ---------------- kernel 1b: g_WhT16[f][j] = fp16(Wh[j][f]) -----------------
__global__ __launch_bounds__(256) void k_whT16() {
    __shared__ float t[32][68];
    int tid = threadIdx.x;
    int j0 = blockIdx.x * 32;
    {
        int j = tid >> 3, fc = (tid & 7) * 8;
        float4 v0 = *(const float4*)&g_Wh[(size_t)(j0 + j) * FOUT + fc];
        float4 v1 = *(const float4*)&g_Wh[(size_t)(j0 + j) * FOUT + fc + 4];
        t[j][fc + 0] = v0.x; t[j][fc + 1] = v0.y; t[j][fc + 2] = v0.z; t[j][fc + 3] = v0.w;
        t[j][fc + 4] = v1.x; t[j][fc + 5] = v1.y; t[j][fc + 6] = v1.z; t[j][fc + 7] = v1.w;
    }
    __syncthreads();
    {
        int f = tid >> 2, jc = (tid & 3) * 8;
        __half2 h[4];
#pragma unroll
        for (int q = 0; q < 4; q++)
            h[q] = __floats2half2_rn(t[jc + 2 * q][f], t[jc + 2 * q + 1][f]);
        uint4 o;
        o.x = *(uint32_t*)&h[0]; o.y = *(uint32_t*)&h[1];
        o.z = *(uint32_t*)&h[2]; o.w = *(uint32_t*)&h[3];
        *(uint4*)&g_WhT16[(size_t)f * N + j0 + jc] = o;
    }
}

// ---------------- kernel 2: s1 = Wh@a1, s2 = Wh@a2 --------------------------
__global__ __launch_bounds__(256) void k_s12(const float* __restrict__ a) {
    int warp = (blockIdx.x * blockDim.x + threadIdx.x) >> 5;
    int lane = threadIdx.x & 31;
    if (warp >= N) return;
    const float* whr = g_Wh + (size_t)warp * FOUT;
    float v0 = whr[lane], v1 = whr[lane + 32];
    float p1 = v0 * a[lane]      + v1 * a[lane + 32];
    float p2 = v0 * a[64 + lane] + v1 * a[96 + lane];
#pragma unroll
    for (int off = 16; off > 0; off >>= 1) {
        p1 += __shfl_down_sync(0xffffffffu, p1, off);
        p2 += __shfl_down_sync(0xffffffffu, p2, off);
    }
    if (lane == 0) { g_s1[warp] = p1; g_s2[warp] = p2; }
}

// ---------------- kernel 3: global max of s2 --------------------------------
__global__ __launch_bounds__(256) void k_max() {
    __shared__ float sm[256];
    int tid = threadIdx.x;
    float m = -INFINITY;
    for (int i = tid; i < N; i += 256) m = fmaxf(m, g_s2[i]);
    sm[tid] = m;
    __syncthreads();
#pragma unroll
    for (int s = 128; s > 0; s >>= 1) {
        if (tid < s) sm[tid] = fmaxf(sm[tid], sm[tid + s]);
        __syncthreads();
    }
    if (tid == 0) g_s2max = sm[0];
}

// ---------------- kernel 3b: per-node softmax factors -----------------------
// exp(lrelu(s1_i+s2_j) - m_i) == max(E1_i*F1_j, E2_i*F2_j); all exponents <= 0.
__global__ __launch_bounds__(256) void k_factors() {
    int i = blockIdx.x * 256 + threadIdx.x;
    float s2m = g_s2max;
    float x = g_s1[i] + s2m;
    float m = fmaxf(x, ALPHA * x);
    g_E1[i] = expf(x - m);
    g_E2[i] = expf(ALPHA * x - m);
    float y = g_s2[i] - s2m;
    g_F1[i] = expf(y);
    g_F2[i] = expf(ALPHA * y);
}

// ---------------- produce: weights (fp16) + whT tile -> smem buffer ---------
__device__ __forceinline__ void produce_tile(
    __half* __restrict__ wp, __half* __restrict__ whp,
    const int4* av, const uint4 whv,
    const float* __restrict__ E1s, const float* __restrict__ E2s,
    const float* __restrict__ F1s, const float* __restrict__ F2s,
    int jt, int rbase, int a_, int b_, int tid, float* den)
{
    float4 f1 = *(const float4*)&F1s[jt + b_ * 4];
    float4 f2 = *(const float4*)&F2s[jt + b_ * 4];
#pragma unroll
    for (int p = 0; p < 4; p++) {
        int r = rbase + p * 4 + a_;
        float e1 = E1s[r], e2 = E2s[r];
        float w0 = (av[p].x > 0) ? fmaxf(e1 * f1.x, e2 * f2.x) : 0.f;
        float w1 = (av[p].y > 0) ? fmaxf(e1 * f1.y, e2 * f2.y) : 0.f;
        float w2 = (av[p].z > 0) ? fmaxf(e1 * f1.z, e2 * f2.z) : 0.f;
        float w3 = (av[p].w > 0) ? fmaxf(e1 * f1.w, e2 * f2.w) : 0.f;
        den[p] += (w0 + w1) + (w2 + w3);
        __half2 h01 = __floats2half2_rn(w0, w1);
        __half2 h23 = __floats2half2_rn(w2, w3);
        uint2 u;
        u.x = *(uint32_t*)&h01;
        u.y = *(uint32_t*)&h23;
        *(uint2*)&wp[r * W16_STR + b_ * 4] = u;
    }
    // whT tile: 64 f-rows x 32 j fp16; thread (tid>>2) = f-row, (tid&3) = 8-j chunk
    *(uint4*)&whp[(tid >> 2) * W16_STR + (tid & 3) * 8] = whv;
}

// ---------------- kernel 4: pipelined fp16 mma attention --------------------
__global__ __launch_bounds__(256, 2) void k_attn_mma(const int* __restrict__ adj) {
    extern __shared__ char dyn[];
    float*  E1s   = (float*)dyn;
    float*  E2s   = E1s + 128;
    float*  F1s   = E2s + 128;
    float*  F2s   = F1s + JSLICE;
    __half* w_sm  = (__half*)(F2s + JSLICE);
    __half* wh_sm = w_sm + 2 * W_BUF;

    int tid  = threadIdx.x;
    int lane = tid & 31;
    int wid  = tid >> 5;
    int tile  = blockIdx.x >> 2;
    int slice = blockIdx.x & (S_SLICES - 1);
    int i0 = tile * TI;
    int j0 = slice * JSLICE;

    if (tid < TI) {
        E1s[tid] = g_E1[i0 + tid];
        E2s[tid] = g_E2[i0 + tid];
    }
#pragma unroll
    for (int q = 0; q < JSLICE / 256; q++) {
        F1s[tid + q * 256] = g_F1[j0 + tid + q * 256];
        F2s[tid + q * 256] = g_F2[j0 + tid + q * 256];
    }

    int a_ = lane >> 3;        // 0..3: row offset
    int b_ = lane & 7;         // 0..7: 4-j column group
    int g  = lane >> 2;        // mma group id
    int t  = lane & 3;         // mma thread-in-group

    int rbase = wid * 16;                 // w-phase rows
    int mgrp  = (wid >> 1) * 32;          // mma rowgroup
    int nh    = (wid & 1) * 4;            // mma n-half (4 n8-tiles)

    const int* rp[4];
#pragma unroll
    for (int p = 0; p < 4; p++)
        rp[p] = adj + (size_t)(i0 + rbase + p * 4 + a_) * N + j0;
    const __half* whq = g_WhT16 + (size_t)(tid >> 2) * N + j0 + (tid & 3) * 8;

    float den[4];
#pragma unroll
    for (int p = 0; p < 4; p++) den[p] = 0.f;
    float acc[2][4][4];
#pragma unroll
    for (int mt = 0; mt < 2; mt++)
#pragma unroll
        for (int n = 0; n < 4; n++)
#pragma unroll
            for (int c = 0; c < 4; c++) acc[mt][n][c] = 0.f;

    // ---- preamble: load + produce tile 0, prefetch tile 1 ----
    int4 av[4];
    uint4 whv;
#pragma unroll
    for (int p = 0; p < 4; p++) av[p] = *(const int4*)&rp[p][b_ * 4];
    whv = *(const uint4*)whq;
    __syncthreads();   // E/F tiles ready
    produce_tile(w_sm, wh_sm, av, whv, E1s, E2s, F1s, F2s, 0,
                 rbase, a_, b_, tid, den);
#pragma unroll
    for (int p = 0; p < 4; p++) av[p] = *(const int4*)&rp[p][KT + b_ * 4];
    whv = *(const uint4*)(whq + KT);
    __syncthreads();   // buf0 published

    for (int it = 0; it < NITER; it++) {
        const __half* wp  = w_sm  + (it & 1) * W_BUF;
        const __half* whp = wh_sm + (it & 1) * WH_BUF;

        // ---- mma phase: 2 k16-steps x 2 m16 x 4 n8 ----
#pragma unroll
        for (int k = 0; k < 2; k++) {
            int k0 = k * 16;
            uint32_t bfr[4][2];
#pragma unroll
            for (int n = 0; n < 4; n++) {
                const __half* bp = whp + ((nh + n) * 8 + g) * W16_STR + k0 + 2 * t;
                bfr[n][0] = *(const uint32_t*)bp;
                bfr[n][1] = *(const uint32_t*)(bp + 8);
            }
#pragma unroll
            for (int mt = 0; mt < 2; mt++) {
                int r0 = mgrp + mt * 16 + g;
                const __half* ap = wp + r0 * W16_STR + k0 + 2 * t;
                uint32_t afr[4];
                afr[0] = *(const uint32_t*)ap;
                afr[1] = *(const uint32_t*)(ap + 8 * W16_STR);
                afr[2] = *(const uint32_t*)(ap + 8);
                afr[3] = *(const uint32_t*)(ap + 8 * W16_STR + 8);
#pragma unroll
                for (int n = 0; n < 4; n++) mma16(acc[mt][n], afr, bfr[n]);
            }
        }

        // ---- produce tile it+1 into other buffer, prefetch it+2 ----
        if (it + 1 < NITER) {
            produce_tile(w_sm + ((it + 1) & 1) * W_BUF,
                         wh_sm + ((it + 1) & 1) * WH_BUF,
                         av, whv, E1s, E2s, F1s, F2s, (it + 1) * KT,
                         rbase, a_, b_, tid, den);
            if (it + 2 < NITER) {
                int jn = (it + 2) * KT;
#pragma unroll
                for (int p = 0; p < 4; p++)
                    av[p] = *(const int4*)&rp[p][jn + b_ * 4];
                whv = *(const uint4*)(whq + jn);
            }
        }
        __syncthreads();
    }

    // ---- denominator: reduce across 8 lanes sharing each row ----
#pragma unroll
    for (int p = 0; p < 4; p++) {
        den[p] += __shfl_down_sync(0xffffffffu, den[p], 4, 8);
        den[p] += __shfl_down_sync(0xffffffffu, den[p], 2, 8);
        den[p] += __shfl_down_sync(0xffffffffu, den[p], 1, 8);
    }
    if (b_ == 0) {
#pragma unroll
        for (int p = 0; p < 4; p++)
            g_pden[(size_t)slice * N + i0 + rbase + p * 4 + a_] = den[p];
    }

    // ---- numerator partials ----
#pragma unroll
    for (int mt = 0; mt < 2; mt++) {
#pragma unroll
        for (int n = 0; n < 4; n++) {
            int r0 = mgrp + mt * 16 + g;
            size_t base = ((size_t)slice * N + i0 + r0) * FOUT + (nh + n) * 8 + 2 * t;
            *(float2*)&g_pnum[base] = make_float2(acc[mt][n][0], acc[mt][n][1]);
            *(float2*)&g_pnum[base + 8 * FOUT] = make_float2(acc[mt][n][2], acc[mt][n][3]);
        }
    }
}

// ---------------- kernel 5: combine slices, normalize, elu ------------------
__global__ __launch_bounds__(256) void k_reduce(float* __restrict__ out) {
    int t = blockIdx.x * blockDim.x + threadIdx.x;
    if (t >= N * FOUT / 4) return;
    int i = t >> 4, c4 = (t & 15) << 2;
    float sx = 0.f, sy = 0.f, sz = 0.f, sw = 0.f, d = 0.f;
#pragma unroll
    for (int s = 0; s < S_SLICES; s++) {
        float4 v = *(const float4*)&g_pnum[((size_t)s * N + i) * FOUT + c4];
        sx += v.x; sy += v.y; sz += v.z; sw += v.w;
        d  += g_pden[(size_t)s * N + i];
    }
    float inv = 1.f / d;
    float ox = sx * inv, oy = sy * inv, oz = sz * inv, ow = sw * inv;
    float4 o;
    o.x = ox > 0.f ? ox : expm1f(ox);
    o.y = oy > 0.f ? oy : expm1f(oy);
    o.z = oz > 0.f ? oz : expm1f(oz);
    o.w = ow > 0.f ? ow : expm1f(ow);
    *(float4*)&out[(size_t)i * FOUT + c4] = o;
}

// ---------------------------------------------------------------------------
extern "C" void kernel_launch(void* const* d_in, const int* in_sizes, int n_in,
                              void* d_out, int out_size) {
    const float* h   = (const float*)d_in[0];
    const float* W   = (const float*)d_in[1];
    const float* a   = (const float*)d_in[2];
    const int*   adj = (const int*)d_in[3];
    float* out = (float*)d_out;

    static int attr_set = 0;
    if (!attr_set) {
        cudaFuncSetAttribute(k_attn_mma,
                             cudaFuncAttributeMaxDynamicSharedMemorySize, SMEM_BYTES);
        attr_set = 1;
    }

    k_gemm<<<N / GTI, 256>>>(h, W);
    k_whT16<<<N / 32, 256>>>();
    k_s12<<<N / 8, 256>>>(a);
    k_max<<<1, 256>>>();
    k_factors<<<N / 256, 256>>>();
    k_attn_mma<<<(N / TI) * S_SLICES, 256, SMEM_BYTES>>>(adj);
    k_reduce<<<(N * FOUT / 4) / 256, 256>>>(out);
}